// round 16
// baseline (speedup 1.0000x reference)
#include <cuda_runtime.h>
#include <cuda_fp16.h>
#include <cstdint>

// Problem constants
#define NN   131072      // total nodes (B*N)
#define DIMF 128         // embedding dim
#define EDG  1048576     // edges
#define INF  74          // input feats

// ---------------- device scratch (allocation-free rule) ----------------
__device__ __align__(16) __half g_hA[NN * DIMF];   // 32MB ping
__device__ __align__(16) __half g_hB[NN * DIMF];   // 32MB pong
__device__ float g_nsrc[NN];
__device__ float g_ndst[NN];
__device__ int   g_deg_out[NN];
__device__ int   g_deg_in[NN];
__device__ int   g_cursor[NN];     // prefilled with rstart; fill atomically bumps
__device__ int   g_rstart[NN];
__device__ int   g_csr[EDG];
__device__ int   g_bsum[128];

#define KP_I 80          // init K padded 74 -> 80
// pre-transposed weights: layers in fp16 (same mantissa as tf32), init in tf32
__device__ __align__(16) __half g_WT1[128 * 128];
__device__ __align__(16) __half g_WT2[128 * 128];
__device__ __align__(16) __half g_WT3[128 * 128];
__device__ float g_WTi[128 * KP_I];

// ---------------- helpers ----------------
__device__ __forceinline__ float to_tf32(float x) {
    uint32_t u;
    asm("cvt.rna.tf32.f32 %0, %1;" : "=r"(u) : "f"(x));
    return __uint_as_float(u);
}

// D += A*B, m16n8k16 fp16 inputs, fp32 accum
__device__ __forceinline__ void mma_f16(float d[4],
                                        uint32_t a0, uint32_t a1, uint32_t a2, uint32_t a3,
                                        uint32_t b0, uint32_t b1) {
    asm volatile(
        "mma.sync.aligned.m16n8k16.row.col.f32.f16.f16.f32 "
        "{%0,%1,%2,%3}, {%4,%5,%6,%7}, {%8,%9}, {%0,%1,%2,%3};"
        : "+f"(d[0]), "+f"(d[1]), "+f"(d[2]), "+f"(d[3])
        : "r"(a0), "r"(a1), "r"(a2), "r"(a3), "r"(b0), "r"(b1));
}

// tf32 variant for the init GEMM (K=74 -> 80, fp32 input)
__device__ __forceinline__ void mma_tf32(float d[4],
                                         uint32_t a0, uint32_t a1, uint32_t a2, uint32_t a3,
                                         uint32_t b0, uint32_t b1) {
    asm volatile(
        "mma.sync.aligned.m16n8k8.row.col.f32.tf32.tf32.f32 "
        "{%0,%1,%2,%3}, {%4,%5,%6,%7}, {%8,%9}, {%0,%1,%2,%3};"
        : "+f"(d[0]), "+f"(d[1]), "+f"(d[2]), "+f"(d[3])
        : "r"(a0), "r"(a1), "r"(a2), "r"(a3), "r"(b0), "r"(b1));
}

// ---------------- preprocessing ----------------
__global__ void k_prep(const float* __restrict__ Wi, const float* __restrict__ W1,
                       const float* __restrict__ W2, const float* __restrict__ W3) {
    int i = blockIdx.x * blockDim.x + threadIdx.x;
    if (i < NN) { g_deg_out[i] = 0; g_deg_in[i] = 0; }
    if (i < 128 * 128) {
        int n = i >> 7, k = i & 127;
        g_WT1[i] = __float2half_rn(W1[k * 128 + n]);
        g_WT2[i] = __float2half_rn(W2[k * 128 + n]);
        g_WT3[i] = __float2half_rn(W3[k * 128 + n]);
    }
    if (i < 128 * KP_I) {
        int n = i / KP_I, k = i - n * KP_I;
        g_WTi[i] = (k < INF) ? to_tf32(Wi[k * 128 + n]) : 0.f;
    }
}

// Vectorized degree count: int4 reads, 4 edges/thread, exactly one pass.
__global__ void k_count(const int* __restrict__ src, const int* __restrict__ dst) {
    int i = blockIdx.x * blockDim.x + threadIdx.x;   // i < EDG/4
    int4 s4 = ((const int4*)src)[i];
    int4 d4 = ((const int4*)dst)[i];
    atomicAdd(&g_deg_out[s4.x], 1);
    atomicAdd(&g_deg_out[s4.y], 1);
    atomicAdd(&g_deg_out[s4.z], 1);
    atomicAdd(&g_deg_out[s4.w], 1);
    atomicAdd(&g_deg_in[d4.x], 1);
    atomicAdd(&g_deg_in[d4.y], 1);
    atomicAdd(&g_deg_in[d4.z], 1);
    atomicAdd(&g_deg_in[d4.w], 1);
}

// Block scan of deg_in (1024/block) via warp shuffles (2 barriers) + norms.
__global__ void k_scanA() {
    __shared__ int wsum[32];
    int i = blockIdx.x * 1024 + threadIdx.x;
    int lane = threadIdx.x & 31, warp = threadIdx.x >> 5;
    int v = g_deg_in[i];
    int vo = g_deg_out[i];
    g_nsrc[i] = rsqrtf((float)max(vo, 1));
    g_ndst[i] = rsqrtf((float)max(v, 1));
    int s = v;
#pragma unroll
    for (int off = 1; off < 32; off <<= 1) {
        int t = __shfl_up_sync(0xffffffffu, s, off);
        if (lane >= off) s += t;
    }
    if (lane == 31) wsum[warp] = s;
    __syncthreads();
    if (warp == 0) {
        int w = wsum[lane];
#pragma unroll
        for (int off = 1; off < 32; off <<= 1) {
            int t = __shfl_up_sync(0xffffffffu, w, off);
            if (lane >= off) w += t;
        }
        wsum[lane] = w;
    }
    __syncthreads();
    int base = (warp > 0) ? wsum[warp - 1] : 0;
    g_rstart[i] = base + s - v;               // exclusive (block-local)
    if (threadIdx.x == 1023) g_bsum[blockIdx.x] = wsum[31];
}

// Finalize rstart with cross-block offsets (redundant 128-wide scan per block),
// and prefill cursor with the absolute row start.
__global__ void k_scanC2() {
    __shared__ int sB[128];
    int tid = threadIdx.x;
    if (tid < 128) sB[tid] = g_bsum[tid];
    __syncthreads();
#pragma unroll
    for (int off = 1; off < 128; off <<= 1) {
        int t = (tid >= off && tid < 128) ? sB[tid - off] : 0;
        __syncthreads();
        if (tid < 128) sB[tid] += t;
        __syncthreads();
    }
    int j = blockIdx.x >> 2;
    int boff = sB[j] - g_bsum[j];
    int i = blockIdx.x * 256 + tid;
    int rs = g_rstart[i] + boff;
    g_rstart[i] = rs;
    g_cursor[i] = rs;                          // fill bumps this directly
}

// ---------------- tile strides ----------------
#define LDH 136          // layer tiles (halves): 128 k + 8 pad, conflict-free
#define LDI 84           // init tiles (floats): 80 k + 4 pad

#define FILL_BLOCKS (EDG / 4 / 256)   // 1024
#define INIT_BLOCKS (NN / 64)         // 2048

// ================= fused fill + init kernel =================
// Heterogeneous blocks: [0, FILL_BLOCKS) do the CSR bucket fill (int4 edges,
// cursor atomics); the rest run the init GEMM (BM=64, tf32, 2 CTAs/SM).
// The two tasks are independent (fill needs scanC2's cursor; init needs
// scanA's nsrc + prep's WTi) and overlap on the device in one launch.
__global__ void __launch_bounds__(256, 2)
k_fill_init(const int* __restrict__ src, const int* __restrict__ dst,
            const float* __restrict__ x) {
    const int tid = threadIdx.x;

    if (blockIdx.x < FILL_BLOCKS) {
        // ---- CSR fill ----
        int i = blockIdx.x * 256 + tid;   // i < EDG/4
        int4 s4 = ((const int4*)src)[i];
        int4 d4 = ((const int4*)dst)[i];
        g_csr[atomicAdd(&g_cursor[d4.x], 1)] = s4.x;
        g_csr[atomicAdd(&g_cursor[d4.y], 1)] = s4.y;
        g_csr[atomicAdd(&g_cursor[d4.z], 1)] = s4.z;
        g_csr[atomicAdd(&g_cursor[d4.w], 1)] = s4.w;
        return;
    }

    // ---- init GEMM: g_hA = fp16((x @ W_init) * nsrc) ----
    extern __shared__ float sm[];
    float* As = sm;                    // [64][LDI]
    float* Bs = sm + 64 * LDI;         // [128][LDI]
    const int lane = tid & 31, warp = tid >> 5;
    const int rowBase = (blockIdx.x - FILL_BLOCKS) * 64;

    {
        const float4* Wt4 = (const float4*)g_WTi;
        for (int idx = tid; idx < 128 * (KP_I / 4); idx += 256) {
            int n = idx / (KP_I / 4), kq = idx - n * (KP_I / 4);
            *(float4*)&Bs[n * LDI + kq * 4] = Wt4[idx];
        }
    }
    for (int idx = tid; idx < 64 * KP_I; idx += 256) {
        int r = idx / KP_I, k = idx - r * KP_I;
        float v = (k < INF) ? to_tf32(x[(size_t)(rowBase + r) * INF + k]) : 0.f;
        As[r * LDI + k] = v;
    }
    __syncthreads();

    const int wr = warp >> 2, wc = warp & 3;   // 2x4 warp grid
    const int m0 = wr * 32, n0 = wc * 32;
    const int g = lane >> 2, tig = lane & 3;

    float D[2][4][4];
#pragma unroll
    for (int i = 0; i < 2; i++)
#pragma unroll
        for (int j = 0; j < 4; j++)
#pragma unroll
            for (int q = 0; q < 4; q++) D[i][j][q] = 0.f;

    const uint32_t* Au = (const uint32_t*)As;
    const uint32_t* Bu = (const uint32_t*)Bs;

#pragma unroll
    for (int k0 = 0; k0 < KP_I; k0 += 8) {
        uint32_t a[2][4];
#pragma unroll
        for (int i = 0; i < 2; i++) {
            int mr = m0 + i * 16 + g;
            a[i][0] = Au[mr * LDI + k0 + tig];
            a[i][1] = Au[(mr + 8) * LDI + k0 + tig];
            a[i][2] = Au[mr * LDI + k0 + tig + 4];
            a[i][3] = Au[(mr + 8) * LDI + k0 + tig + 4];
        }
        uint32_t b[4][2];
#pragma unroll
        for (int j = 0; j < 4; j++) {
            int nc = n0 + j * 8 + g;
            b[j][0] = Bu[nc * LDI + k0 + tig];
            b[j][1] = Bu[nc * LDI + k0 + tig + 4];
        }
#pragma unroll
        for (int i = 0; i < 2; i++)
#pragma unroll
            for (int j = 0; j < 4; j++)
                mma_tf32(D[i][j], a[i][0], a[i][1], a[i][2], a[i][3], b[j][0], b[j][1]);
    }

#pragma unroll
    for (int i = 0; i < 2; i++) {
        int r0 = rowBase + m0 + i * 16 + g;
        float ns0 = g_nsrc[r0];
        float ns1 = g_nsrc[r0 + 8];
#pragma unroll
        for (int j = 0; j < 4; j++) {
            int col = n0 + j * 8 + tig * 2;
            *(__half2*)&g_hA[(size_t)r0 * 128 + col] =
                __floats2half2_rn(D[i][j][0] * ns0, D[i][j][1] * ns0);
            *(__half2*)&g_hA[(size_t)(r0 + 8) * 128 + col] =
                __floats2half2_rn(D[i][j][2] * ns1, D[i][j][3] * ns1);
        }
    }
}

// ================= fused layer kernel (fp16 MMA, 2 CTAs/SM) — R12/R14 winner =================
template <int MODE>
__global__ void __launch_bounds__(512, 2)
k_layer_mma(const __half* __restrict__ hn,
            const __half* __restrict__ Wt,
            const float* __restrict__ bias,
            void* __restrict__ outv) {
    extern __shared__ __half smh[];
    __half* As = smh;                  // [128][LDH]
    __half* Bs = smh + 128 * LDH;      // [128][LDH]  Bs[n][k] = fp16(W[k][n])
    const int tid = threadIdx.x;
    const int lane = tid & 31, warp = tid >> 5;
    const int rowBase = blockIdx.x * 128;

    // ---- stage B from pre-transposed fp16 WT (uint4 = 8 halves) ----
    {
        const uint4* Wt4 = (const uint4*)Wt;
        for (int idx = tid; idx < 128 * 16; idx += 512) {
            int n = idx >> 4, q = idx & 15;
            *(uint4*)&Bs[n * LDH + q * 8] = Wt4[idx];
        }
    }

    // ---- per-warp row metadata prefetch (lanes 0-7, then shfl) ----
    int myJ0 = 0, myCnt = 0;
    float myNd = 0.f;
    if (lane < 8) {
        int n = rowBase + warp * 8 + lane;
        myJ0 = g_rstart[n];
        myCnt = g_deg_in[n];
        myNd = g_ndst[n];
    }

    // ---- gather: 8 rows per warp; 2 edges per LDG; 4-pair window ----
    const uint4* h4 = (const uint4*)hn;    // 8 halves per chunk; row = 16 chunks
    const int sub = lane >> 4;             // edge of the pair (0/1)
    const int ch  = lane & 15;             // k-chunk within row
    for (int rr = 0; rr < 8; ++rr) {
        int r = warp * 8 + rr;
        int j0 = __shfl_sync(0xffffffffu, myJ0, rr);
        int cnt = __shfl_sync(0xffffffffu, myCnt, rr);
        float nd = __shfl_sync(0xffffffffu, myNd, rr);
        float acc[8] = {0.f, 0.f, 0.f, 0.f, 0.f, 0.f, 0.f, 0.f};
#pragma unroll 1
        for (int j = 0; j < cnt; j += 8) {
            uint4 v[4];
#pragma unroll
            for (int w = 0; w < 4; ++w) {
                int e = j + 2 * w + sub;
                v[w] = make_uint4(0u, 0u, 0u, 0u);
                if (e < cnt) {
                    int s = g_csr[j0 + e];
                    v[w] = h4[s * 16 + ch];
                }
            }
#pragma unroll
            for (int w = 0; w < 4; ++w) {
                float2 f0 = __half22float2(*(__half2*)&v[w].x);
                float2 f1 = __half22float2(*(__half2*)&v[w].y);
                float2 f2 = __half22float2(*(__half2*)&v[w].z);
                float2 f3 = __half22float2(*(__half2*)&v[w].w);
                acc[0] += f0.x; acc[1] += f0.y;
                acc[2] += f1.x; acc[3] += f1.y;
                acc[4] += f2.x; acc[5] += f2.y;
                acc[6] += f3.x; acc[7] += f3.y;
            }
        }
#pragma unroll
        for (int q = 0; q < 8; ++q) {
            float o = __shfl_down_sync(0xffffffffu, acc[q], 16);
            acc[q] += o;
        }
        if (lane < 16) {
            uint4 st;
            ((__half2*)&st)[0] = __floats2half2_rn(acc[0] * nd, acc[1] * nd);
            ((__half2*)&st)[1] = __floats2half2_rn(acc[2] * nd, acc[3] * nd);
            ((__half2*)&st)[2] = __floats2half2_rn(acc[4] * nd, acc[5] * nd);
            ((__half2*)&st)[3] = __floats2half2_rn(acc[6] * nd, acc[7] * nd);
            *(uint4*)&As[r * LDH + ch * 8] = st;
        }
    }
    __syncthreads();

    // ---- Phase 2: fp16 MMA, warp 32x32 tile; warp grid 4x4 ----
    const int wr = warp >> 2, wc = warp & 3;
    const int m0 = wr * 32, n0 = wc * 32;
    const int g = lane >> 2, tig = lane & 3;

    float D[2][4][4];
#pragma unroll
    for (int i = 0; i < 2; i++)
#pragma unroll
        for (int j = 0; j < 4; j++)
#pragma unroll
            for (int q = 0; q < 4; q++) D[i][j][q] = 0.f;

#pragma unroll
    for (int k0 = 0; k0 < 128; k0 += 16) {
        uint32_t a[2][4];
#pragma unroll
        for (int i = 0; i < 2; i++) {
            int mr = m0 + i * 16 + g;
            a[i][0] = *(const uint32_t*)&As[mr * LDH + k0 + 2 * tig];
            a[i][1] = *(const uint32_t*)&As[(mr + 8) * LDH + k0 + 2 * tig];
            a[i][2] = *(const uint32_t*)&As[mr * LDH + k0 + 2 * tig + 8];
            a[i][3] = *(const uint32_t*)&As[(mr + 8) * LDH + k0 + 2 * tig + 8];
        }
        uint32_t b[4][2];
#pragma unroll
        for (int j = 0; j < 4; j++) {
            int nc = n0 + j * 8 + g;
            b[j][0] = *(const uint32_t*)&Bs[nc * LDH + k0 + 2 * tig];
            b[j][1] = *(const uint32_t*)&Bs[nc * LDH + k0 + 2 * tig + 8];
        }
#pragma unroll
        for (int i = 0; i < 2; i++)
#pragma unroll
            for (int j = 0; j < 4; j++)
                mma_f16(D[i][j], a[i][0], a[i][1], a[i][2], a[i][3], b[j][0], b[j][1]);
    }

    // ---- Epilogue ----
#pragma unroll
    for (int i = 0; i < 2; i++) {
        int r0 = rowBase + m0 + i * 16 + g;
        float ns0 = (MODE == 1) ? g_nsrc[r0] : 1.f;
        float ns1 = (MODE == 1) ? g_nsrc[r0 + 8] : 1.f;
#pragma unroll
        for (int j = 0; j < 4; j++) {
            int col = n0 + j * 8 + tig * 2;
            float bx = bias[col], by = bias[col + 1];
            float v0x = fmaxf(D[i][j][0] + bx, 0.f) * ns0;
            float v0y = fmaxf(D[i][j][1] + by, 0.f) * ns0;
            float v1x = fmaxf(D[i][j][2] + bx, 0.f) * ns1;
            float v1y = fmaxf(D[i][j][3] + by, 0.f) * ns1;
            if (MODE == 1) {
                __half* oh = (__half*)outv;
                *(__half2*)&oh[(size_t)r0 * 128 + col] = __floats2half2_rn(v0x, v0y);
                *(__half2*)&oh[(size_t)(r0 + 8) * 128 + col] = __floats2half2_rn(v1x, v1y);
            } else {
                float* of = (float*)outv;
                *(float2*)&of[(size_t)r0 * 128 + col] = make_float2(v0x, v0y);
                *(float2*)&of[(size_t)(r0 + 8) * 128 + col] = make_float2(v1x, v1y);
            }
        }
    }
}

// ---------------- launch ----------------
extern "C" void kernel_launch(void* const* d_in, const int* in_sizes, int n_in,
                              void* d_out, int out_size) {
    (void)in_sizes; (void)n_in; (void)out_size;
    const float* x   = (const float*)d_in[0];
    const int*   src = (const int*)d_in[1];
    const int*   dst = (const int*)d_in[2];
    const float* Wi  = (const float*)d_in[3];
    const float* W1  = (const float*)d_in[4];
    const float* b1  = (const float*)d_in[5];
    const float* W2  = (const float*)d_in[6];
    const float* b2  = (const float*)d_in[7];
    const float* W3  = (const float*)d_in[8];
    const float* b3  = (const float*)d_in[9];

    const int SMEM_LAYER = (2 * 128 * LDH) * 2;       // 69,632 B -> 2 CTAs/SM
    const int SMEM_INIT  = ((64 + 128) * LDI) * 4;    // 64,512 B -> 2 CTAs/SM

    cudaFuncSetAttribute(k_fill_init, cudaFuncAttributeMaxDynamicSharedMemorySize, SMEM_INIT);
    cudaFuncSetAttribute(k_layer_mma<1>, cudaFuncAttributeMaxDynamicSharedMemorySize, SMEM_LAYER);
    cudaFuncSetAttribute(k_layer_mma<2>, cudaFuncAttributeMaxDynamicSharedMemorySize, SMEM_LAYER);

    __half *hA, *hB, *wt1, *wt2, *wt3;
    cudaGetSymbolAddress((void**)&hA, g_hA);
    cudaGetSymbolAddress((void**)&hB, g_hB);
    cudaGetSymbolAddress((void**)&wt1, g_WT1);
    cudaGetSymbolAddress((void**)&wt2, g_WT2);
    cudaGetSymbolAddress((void**)&wt3, g_WT3);

    // graph preprocessing (4 launches; fill and init fused/overlapped)
    k_prep<<<NN / 256, 256>>>(Wi, W1, W2, W3);
    k_count<<<EDG / 4 / 256, 256>>>(src, dst);
    k_scanA<<<NN / 1024, 1024>>>();
    k_scanC2<<<NN / 256, 256>>>();

    // CSR fill ∥ init GEMM (independent; one heterogeneous launch)
    k_fill_init<<<FILL_BLOCKS + INIT_BLOCKS, 256, SMEM_INIT>>>(src, dst, x);

    // 3 GCN layers (fused gather+GEMM; layer 3 writes fp32 d_out)
    k_layer_mma<1><<<NN / 128, 512, SMEM_LAYER>>>(hA, wt1, b1, (void*)hB);
    k_layer_mma<1><<<NN / 128, 512, SMEM_LAYER>>>(hB, wt2, b2, (void*)hA);
    k_layer_mma<2><<<NN / 128, 512, SMEM_LAYER>>>(hA, wt3, b3, d_out);
}

// round 17
// speedup vs baseline: 1.0110x; 1.0110x over previous
#include <cuda_runtime.h>
#include <cuda_fp16.h>
#include <cstdint>

// Problem constants
#define NN   131072      // total nodes (B*N)
#define DIMF 128         // embedding dim
#define EDG  1048576     // edges
#define INF  74          // input feats

// ---------------- device scratch (allocation-free rule) ----------------
__device__ __align__(16) __half g_hA[NN * DIMF];   // 32MB ping
__device__ __align__(16) __half g_hB[NN * DIMF];   // 32MB pong
__device__ float g_nsrc[NN];
__device__ float g_ndst[NN];
__device__ int   g_deg_out[NN];
__device__ int   g_deg_in[NN];
__device__ int   g_cursor[NN];     // prefilled with rstart; fill atomically bumps
__device__ int   g_rstart[NN];
__device__ int   g_csr[EDG];
__device__ int   g_bsum[128];

#define KP_I 80          // init K padded 74 -> 80
// pre-transposed weights: layers in fp16 (same mantissa as tf32), init in tf32
__device__ __align__(16) __half g_WT1[128 * 128];
__device__ __align__(16) __half g_WT2[128 * 128];
__device__ __align__(16) __half g_WT3[128 * 128];
__device__ float g_WTi[128 * KP_I];

// ---------------- helpers ----------------
__device__ __forceinline__ float to_tf32(float x) {
    uint32_t u;
    asm("cvt.rna.tf32.f32 %0, %1;" : "=r"(u) : "f"(x));
    return __uint_as_float(u);
}

// D += A*B, m16n8k16 fp16 inputs, fp32 accum
__device__ __forceinline__ void mma_f16(float d[4],
                                        uint32_t a0, uint32_t a1, uint32_t a2, uint32_t a3,
                                        uint32_t b0, uint32_t b1) {
    asm volatile(
        "mma.sync.aligned.m16n8k16.row.col.f32.f16.f16.f32 "
        "{%0,%1,%2,%3}, {%4,%5,%6,%7}, {%8,%9}, {%0,%1,%2,%3};"
        : "+f"(d[0]), "+f"(d[1]), "+f"(d[2]), "+f"(d[3])
        : "r"(a0), "r"(a1), "r"(a2), "r"(a3), "r"(b0), "r"(b1));
}

// tf32 variant for the init GEMM (K=74 -> 80, fp32 input)
__device__ __forceinline__ void mma_tf32(float d[4],
                                         uint32_t a0, uint32_t a1, uint32_t a2, uint32_t a3,
                                         uint32_t b0, uint32_t b1) {
    asm volatile(
        "mma.sync.aligned.m16n8k8.row.col.f32.tf32.tf32.f32 "
        "{%0,%1,%2,%3}, {%4,%5,%6,%7}, {%8,%9}, {%0,%1,%2,%3};"
        : "+f"(d[0]), "+f"(d[1]), "+f"(d[2]), "+f"(d[3])
        : "r"(a0), "r"(a1), "r"(a2), "r"(a3), "r"(b0), "r"(b1));
}

// ---------------- preprocessing ----------------
__global__ void k_prep(const float* __restrict__ Wi, const float* __restrict__ W1,
                       const float* __restrict__ W2, const float* __restrict__ W3) {
    int i = blockIdx.x * blockDim.x + threadIdx.x;
    if (i < NN) { g_deg_out[i] = 0; g_deg_in[i] = 0; }
    if (i < 128 * 128) {
        int n = i >> 7, k = i & 127;
        g_WT1[i] = __float2half_rn(W1[k * 128 + n]);
        g_WT2[i] = __float2half_rn(W2[k * 128 + n]);
        g_WT3[i] = __float2half_rn(W3[k * 128 + n]);
    }
    if (i < 128 * KP_I) {
        int n = i / KP_I, k = i - n * KP_I;
        g_WTi[i] = (k < INF) ? to_tf32(Wi[k * 128 + n]) : 0.f;
    }
}

// Vectorized degree count: int4 reads, 4 edges/thread, exactly one pass.
__global__ void k_count(const int* __restrict__ src, const int* __restrict__ dst) {
    int i = blockIdx.x * blockDim.x + threadIdx.x;   // i < EDG/4
    int4 s4 = ((const int4*)src)[i];
    int4 d4 = ((const int4*)dst)[i];
    atomicAdd(&g_deg_out[s4.x], 1);
    atomicAdd(&g_deg_out[s4.y], 1);
    atomicAdd(&g_deg_out[s4.z], 1);
    atomicAdd(&g_deg_out[s4.w], 1);
    atomicAdd(&g_deg_in[d4.x], 1);
    atomicAdd(&g_deg_in[d4.y], 1);
    atomicAdd(&g_deg_in[d4.z], 1);
    atomicAdd(&g_deg_in[d4.w], 1);
}

// Block scan of deg_in (1024/block) via warp shuffles (2 barriers) + norms.
__global__ void k_scanA() {
    __shared__ int wsum[32];
    int i = blockIdx.x * 1024 + threadIdx.x;
    int lane = threadIdx.x & 31, warp = threadIdx.x >> 5;
    int v = g_deg_in[i];
    int vo = g_deg_out[i];
    g_nsrc[i] = rsqrtf((float)max(vo, 1));
    g_ndst[i] = rsqrtf((float)max(v, 1));
    int s = v;
#pragma unroll
    for (int off = 1; off < 32; off <<= 1) {
        int t = __shfl_up_sync(0xffffffffu, s, off);
        if (lane >= off) s += t;
    }
    if (lane == 31) wsum[warp] = s;
    __syncthreads();
    if (warp == 0) {
        int w = wsum[lane];
#pragma unroll
        for (int off = 1; off < 32; off <<= 1) {
            int t = __shfl_up_sync(0xffffffffu, w, off);
            if (lane >= off) w += t;
        }
        wsum[lane] = w;
    }
    __syncthreads();
    int base = (warp > 0) ? wsum[warp - 1] : 0;
    g_rstart[i] = base + s - v;               // exclusive (block-local)
    if (threadIdx.x == 1023) g_bsum[blockIdx.x] = wsum[31];
}

// Finalize rstart with cross-block offsets (redundant 128-wide scan per block),
// and prefill cursor with the absolute row start.
__global__ void k_scanC2() {
    __shared__ int sB[128];
    int tid = threadIdx.x;
    if (tid < 128) sB[tid] = g_bsum[tid];
    __syncthreads();
#pragma unroll
    for (int off = 1; off < 128; off <<= 1) {
        int t = (tid >= off && tid < 128) ? sB[tid - off] : 0;
        __syncthreads();
        if (tid < 128) sB[tid] += t;
        __syncthreads();
    }
    int j = blockIdx.x >> 2;
    int boff = sB[j] - g_bsum[j];
    int i = blockIdx.x * 256 + tid;
    int rs = g_rstart[i] + boff;
    g_rstart[i] = rs;
    g_cursor[i] = rs;                          // fill bumps this directly
}

// Vectorized CSR fill: int4 reads; atomic on cursor returns the absolute slot.
__global__ void k_fill(const int* __restrict__ src, const int* __restrict__ dst) {
    int i = blockIdx.x * blockDim.x + threadIdx.x;   // i < EDG/4
    int4 s4 = ((const int4*)src)[i];
    int4 d4 = ((const int4*)dst)[i];
    g_csr[atomicAdd(&g_cursor[d4.x], 1)] = s4.x;
    g_csr[atomicAdd(&g_cursor[d4.y], 1)] = s4.y;
    g_csr[atomicAdd(&g_cursor[d4.z], 1)] = s4.z;
    g_csr[atomicAdd(&g_cursor[d4.w], 1)] = s4.w;
}

// ---------------- tile strides ----------------
#define LDH 136          // layer tiles (halves): 128 k + 8 pad, conflict-free
#define LDI 84           // init tiles (floats): 80 k + 4 pad

// ================= fused layer kernel (fp16 MMA, 2 CTAs/SM) =================
// PDL: launched with programmatic stream serialization. Prelude (B staging +
// row metadata — independent of the predecessor's output) runs before
// cudaGridDependencySynchronize(); gather/MMA/epilogue after it.
template <int MODE>
__global__ void __launch_bounds__(512, 2)
k_layer_mma(const __half* __restrict__ hn,
            const __half* __restrict__ Wt,
            const float* __restrict__ bias,
            void* __restrict__ outv) {
    extern __shared__ __half smh[];
    __half* As = smh;                  // [128][LDH]
    __half* Bs = smh + 128 * LDH;      // [128][LDH]  Bs[n][k] = fp16(W[k][n])
    const int tid = threadIdx.x;
    const int lane = tid & 31, warp = tid >> 5;
    const int rowBase = blockIdx.x * 128;

    // ---- prelude: stage B from pre-transposed fp16 WT (uint4 = 8 halves) ----
    {
        const uint4* Wt4 = (const uint4*)Wt;
        for (int idx = tid; idx < 128 * 16; idx += 512) {
            int n = idx >> 4, q = idx & 15;
            *(uint4*)&Bs[n * LDH + q * 8] = Wt4[idx];
        }
    }

    // ---- prelude: per-warp row metadata (lanes 0-7, then shfl) ----
    int myJ0 = 0, myCnt = 0;
    float myNd = 0.f;
    if (lane < 8) {
        int n = rowBase + warp * 8 + lane;
        myJ0 = g_rstart[n];
        myCnt = g_deg_in[n];
        myNd = g_ndst[n];
    }

    // ---- wait for predecessor (producer of hn) ----
    cudaGridDependencySynchronize();

    // ---- gather: 8 rows per warp; 2 edges per LDG; 4-pair window ----
    const uint4* h4 = (const uint4*)hn;    // 8 halves per chunk; row = 16 chunks
    const int sub = lane >> 4;             // edge of the pair (0/1)
    const int ch  = lane & 15;             // k-chunk within row
    for (int rr = 0; rr < 8; ++rr) {
        int r = warp * 8 + rr;
        int j0 = __shfl_sync(0xffffffffu, myJ0, rr);
        int cnt = __shfl_sync(0xffffffffu, myCnt, rr);
        float nd = __shfl_sync(0xffffffffu, myNd, rr);
        float acc[8] = {0.f, 0.f, 0.f, 0.f, 0.f, 0.f, 0.f, 0.f};
#pragma unroll 1
        for (int j = 0; j < cnt; j += 8) {
            uint4 v[4];
#pragma unroll
            for (int w = 0; w < 4; ++w) {
                int e = j + 2 * w + sub;
                v[w] = make_uint4(0u, 0u, 0u, 0u);
                if (e < cnt) {
                    int s = g_csr[j0 + e];
                    v[w] = h4[s * 16 + ch];
                }
            }
#pragma unroll
            for (int w = 0; w < 4; ++w) {
                float2 f0 = __half22float2(*(__half2*)&v[w].x);
                float2 f1 = __half22float2(*(__half2*)&v[w].y);
                float2 f2 = __half22float2(*(__half2*)&v[w].z);
                float2 f3 = __half22float2(*(__half2*)&v[w].w);
                acc[0] += f0.x; acc[1] += f0.y;
                acc[2] += f1.x; acc[3] += f1.y;
                acc[4] += f2.x; acc[5] += f2.y;
                acc[6] += f3.x; acc[7] += f3.y;
            }
        }
#pragma unroll
        for (int q = 0; q < 8; ++q) {
            float o = __shfl_down_sync(0xffffffffu, acc[q], 16);
            acc[q] += o;
        }
        if (lane < 16) {
            uint4 st;
            ((__half2*)&st)[0] = __floats2half2_rn(acc[0] * nd, acc[1] * nd);
            ((__half2*)&st)[1] = __floats2half2_rn(acc[2] * nd, acc[3] * nd);
            ((__half2*)&st)[2] = __floats2half2_rn(acc[4] * nd, acc[5] * nd);
            ((__half2*)&st)[3] = __floats2half2_rn(acc[6] * nd, acc[7] * nd);
            *(uint4*)&As[r * LDH + ch * 8] = st;
        }
    }
    __syncthreads();

    // ---- Phase 2: fp16 MMA, warp 32x32 tile; warp grid 4x4 ----
    const int wr = warp >> 2, wc = warp & 3;
    const int m0 = wr * 32, n0 = wc * 32;
    const int g = lane >> 2, tig = lane & 3;

    float D[2][4][4];
#pragma unroll
    for (int i = 0; i < 2; i++)
#pragma unroll
        for (int j = 0; j < 4; j++)
#pragma unroll
            for (int q = 0; q < 4; q++) D[i][j][q] = 0.f;

#pragma unroll
    for (int k0 = 0; k0 < 128; k0 += 16) {
        uint32_t a[2][4];
#pragma unroll
        for (int i = 0; i < 2; i++) {
            int mr = m0 + i * 16 + g;
            a[i][0] = *(const uint32_t*)&As[mr * LDH + k0 + 2 * tig];
            a[i][1] = *(const uint32_t*)&As[(mr + 8) * LDH + k0 + 2 * tig];
            a[i][2] = *(const uint32_t*)&As[mr * LDH + k0 + 2 * tig + 8];
            a[i][3] = *(const uint32_t*)&As[(mr + 8) * LDH + k0 + 2 * tig + 8];
        }
        uint32_t b[4][2];
#pragma unroll
        for (int j = 0; j < 4; j++) {
            int nc = n0 + j * 8 + g;
            b[j][0] = *(const uint32_t*)&Bs[nc * LDH + k0 + 2 * tig];
            b[j][1] = *(const uint32_t*)&Bs[nc * LDH + k0 + 2 * tig + 8];
        }
#pragma unroll
        for (int i = 0; i < 2; i++)
#pragma unroll
            for (int j = 0; j < 4; j++)
                mma_f16(D[i][j], a[i][0], a[i][1], a[i][2], a[i][3], b[j][0], b[j][1]);
    }

    // ---- Epilogue ----
#pragma unroll
    for (int i = 0; i < 2; i++) {
        int r0 = rowBase + m0 + i * 16 + g;
        float ns0 = (MODE == 1) ? g_nsrc[r0] : 1.f;
        float ns1 = (MODE == 1) ? g_nsrc[r0 + 8] : 1.f;
#pragma unroll
        for (int j = 0; j < 4; j++) {
            int col = n0 + j * 8 + tig * 2;
            float bx = bias[col], by = bias[col + 1];
            float v0x = fmaxf(D[i][j][0] + bx, 0.f) * ns0;
            float v0y = fmaxf(D[i][j][1] + by, 0.f) * ns0;
            float v1x = fmaxf(D[i][j][2] + bx, 0.f) * ns1;
            float v1y = fmaxf(D[i][j][3] + by, 0.f) * ns1;
            if (MODE == 1) {
                __half* oh = (__half*)outv;
                *(__half2*)&oh[(size_t)r0 * 128 + col] = __floats2half2_rn(v0x, v0y);
                *(__half2*)&oh[(size_t)(r0 + 8) * 128 + col] = __floats2half2_rn(v1x, v1y);
            } else {
                float* of = (float*)outv;
                *(float2*)&of[(size_t)r0 * 128 + col] = make_float2(v0x, v0y);
                *(float2*)&of[(size_t)(r0 + 8) * 128 + col] = make_float2(v1x, v1y);
            }
        }
    }
}

// ================= init kernel: BM=64, 256 threads, 2 CTAs/SM — R14/R15 winner =================
__global__ void __launch_bounds__(256, 2)
k_init_mma(const float* __restrict__ x) {
    extern __shared__ float sm[];
    float* As = sm;                    // [64][LDI]
    float* Bs = sm + 64 * LDI;         // [128][LDI]
    const int tid = threadIdx.x;
    const int lane = tid & 31, warp = tid >> 5;
    const int rowBase = blockIdx.x * 64;

    {
        const float4* Wt4 = (const float4*)g_WTi;
        for (int idx = tid; idx < 128 * (KP_I / 4); idx += 256) {
            int n = idx / (KP_I / 4), kq = idx - n * (KP_I / 4);
            *(float4*)&Bs[n * LDI + kq * 4] = Wt4[idx];
        }
    }
    for (int idx = tid; idx < 64 * KP_I; idx += 256) {
        int r = idx / KP_I, k = idx - r * KP_I;
        float v = (k < INF) ? to_tf32(x[(size_t)(rowBase + r) * INF + k]) : 0.f;
        As[r * LDI + k] = v;
    }
    __syncthreads();

    const int wr = warp >> 2, wc = warp & 3;   // 2x4 warp grid
    const int m0 = wr * 32, n0 = wc * 32;
    const int g = lane >> 2, tig = lane & 3;

    float D[2][4][4];
#pragma unroll
    for (int i = 0; i < 2; i++)
#pragma unroll
        for (int j = 0; j < 4; j++)
#pragma unroll
            for (int q = 0; q < 4; q++) D[i][j][q] = 0.f;

    const uint32_t* Au = (const uint32_t*)As;
    const uint32_t* Bu = (const uint32_t*)Bs;

#pragma unroll
    for (int k0 = 0; k0 < KP_I; k0 += 8) {
        uint32_t a[2][4];
#pragma unroll
        for (int i = 0; i < 2; i++) {
            int mr = m0 + i * 16 + g;
            a[i][0] = Au[mr * LDI + k0 + tig];
            a[i][1] = Au[(mr + 8) * LDI + k0 + tig];
            a[i][2] = Au[mr * LDI + k0 + tig + 4];
            a[i][3] = Au[(mr + 8) * LDI + k0 + tig + 4];
        }
        uint32_t b[4][2];
#pragma unroll
        for (int j = 0; j < 4; j++) {
            int nc = n0 + j * 8 + g;
            b[j][0] = Bu[nc * LDI + k0 + tig];
            b[j][1] = Bu[nc * LDI + k0 + tig + 4];
        }
#pragma unroll
        for (int i = 0; i < 2; i++)
#pragma unroll
            for (int j = 0; j < 4; j++)
                mma_tf32(D[i][j], a[i][0], a[i][1], a[i][2], a[i][3], b[j][0], b[j][1]);
    }

#pragma unroll
    for (int i = 0; i < 2; i++) {
        int r0 = rowBase + m0 + i * 16 + g;
        float ns0 = g_nsrc[r0];
        float ns1 = g_nsrc[r0 + 8];
#pragma unroll
        for (int j = 0; j < 4; j++) {
            int col = n0 + j * 8 + tig * 2;
            *(__half2*)&g_hA[(size_t)r0 * 128 + col] =
                __floats2half2_rn(D[i][j][0] * ns0, D[i][j][1] * ns0);
            *(__half2*)&g_hA[(size_t)(r0 + 8) * 128 + col] =
                __floats2half2_rn(D[i][j][2] * ns1, D[i][j][3] * ns1);
        }
    }
}

// ---------------- launch ----------------
extern "C" void kernel_launch(void* const* d_in, const int* in_sizes, int n_in,
                              void* d_out, int out_size) {
    (void)in_sizes; (void)n_in; (void)out_size;
    const float* x   = (const float*)d_in[0];
    const int*   src = (const int*)d_in[1];
    const int*   dst = (const int*)d_in[2];
    const float* Wi  = (const float*)d_in[3];
    const float* W1  = (const float*)d_in[4];
    const float* b1  = (const float*)d_in[5];
    const float* W2  = (const float*)d_in[6];
    const float* b2  = (const float*)d_in[7];
    const float* W3  = (const float*)d_in[8];
    const float* b3  = (const float*)d_in[9];

    const int SMEM_LAYER = (2 * 128 * LDH) * 2;       // 69,632 B -> 2 CTAs/SM
    const int SMEM_INIT  = ((64 + 128) * LDI) * 4;    // 64,512 B -> 2 CTAs/SM

    cudaFuncSetAttribute(k_init_mma, cudaFuncAttributeMaxDynamicSharedMemorySize, SMEM_INIT);
    cudaFuncSetAttribute(k_layer_mma<1>, cudaFuncAttributeMaxDynamicSharedMemorySize, SMEM_LAYER);
    cudaFuncSetAttribute(k_layer_mma<2>, cudaFuncAttributeMaxDynamicSharedMemorySize, SMEM_LAYER);

    __half *hA, *hB, *wt1, *wt2, *wt3;
    cudaGetSymbolAddress((void**)&hA, g_hA);
    cudaGetSymbolAddress((void**)&hB, g_hB);
    cudaGetSymbolAddress((void**)&wt1, g_WT1);
    cudaGetSymbolAddress((void**)&wt2, g_WT2);
    cudaGetSymbolAddress((void**)&wt3, g_WT3);

    // graph preprocessing (5 launches; count/fill vectorized int4, one pass)
    k_prep<<<NN / 256, 256>>>(Wi, W1, W2, W3);
    k_count<<<EDG / 4 / 256, 256>>>(src, dst);
    k_scanA<<<NN / 1024, 1024>>>();
    k_scanC2<<<NN / 256, 256>>>();
    k_fill<<<EDG / 4 / 256, 256>>>(src, dst);

    // g_hA = fp16((x @ W_init) * nrm_src)  — BM=64, 2 CTAs/SM
    k_init_mma<<<NN / 64, 256, SMEM_INIT>>>(x);

    // 3 GCN layers with PDL: prelude (weight staging + metadata) overlaps the
    // predecessor's tail; cudaGridDependencySynchronize gates the gather.
    cudaLaunchAttribute pdl[1];
    pdl[0].id = cudaLaunchAttributeProgrammaticStreamSerialization;
    pdl[0].val.programmaticStreamSerializationAllowed = 1;

    cudaLaunchConfig_t cfg = {};
    cfg.gridDim = dim3(NN / 128, 1, 1);
    cfg.blockDim = dim3(512, 1, 1);
    cfg.dynamicSmemBytes = SMEM_LAYER;
    cfg.stream = 0;
    cfg.attrs = pdl;
    cfg.numAttrs = 1;

    cudaLaunchKernelEx(&cfg, k_layer_mma<1>, (const __half*)hA, (const __half*)wt1,
                       b1, (void*)hB);
    cudaLaunchKernelEx(&cfg, k_layer_mma<1>, (const __half*)hB, (const __half*)wt2,
                       b2, (void*)hA);
    cudaLaunchKernelEx(&cfg, k_layer_mma<2>, (const __half*)hA, (const __half*)wt3,
                       b3, d_out);
}